// round 5
// baseline (speedup 1.0000x reference)
#include <cuda_runtime.h>
#include <cuda_bf16.h>

// FHN IMEX dynamics, (4,4096,2048) fp32, 8 steps.
// One CTA (512 threads) per 2048-element row; 4 elements/thread (one float4).
// s = P - dt*w folding: 5 packed f32x2 FMA-pipe ops + 4 FMNMX per pair per step.
// Higher occupancy (75% cap) to hide memory + pipe latency.

#define FHN_TAU 12.5f
#define FHN_THRESH 0.5f

typedef unsigned long long ull;

union UF { ull u; float2 f; };

__device__ __forceinline__ ull pk2(float lo, float hi) {
    UF r; r.f.x = lo; r.f.y = hi; return r.u;
}
__device__ __forceinline__ ull fma2(ull a, ull b, ull c) {
    ull d; asm("fma.rn.f32x2 %0, %1, %2, %3;" : "=l"(d) : "l"(a), "l"(b), "l"(c)); return d;
}
__device__ __forceinline__ ull mul2(ull a, ull b) {
    ull d; asm("mul.rn.f32x2 %0, %1, %2;" : "=l"(d) : "l"(a), "l"(b)); return d;
}
__device__ __forceinline__ ull clip2(ull x) {
    UF v; v.u = x;
    v.f.x = fminf(fmaxf(v.f.x, -3.0f), 3.0f);
    v.f.y = fminf(fmaxf(v.f.y, -3.0f), 3.0f);
    return v.u;
}

__global__ __launch_bounds__(512, 3)
void fhn_kernel(const float* __restrict__ stim,
                const float* __restrict__ a_p,
                const float* __restrict__ b_p,
                const float* __restrict__ dt_p,
                const int*   __restrict__ ns_p,
                float* __restrict__ out,
                long long N, int writeV)
{
    const int  C    = 2048;
    const int  t    = threadIdx.x;
    const long long base = (long long)blockIdx.x * C;

    // ---- load 4 elements as one coalesced float4 (512 x 4 = 2048) ----
    const float4* s4 = reinterpret_cast<const float4*>(stim + base);
    float4 x = s4[t];

    // ---- row max(|x|) reduction ----
    float m = fmaxf(fmaxf(fabsf(x.x), fabsf(x.y)), fmaxf(fabsf(x.z), fabsf(x.w)));
    #pragma unroll
    for (int o = 16; o > 0; o >>= 1)
        m = fmaxf(m, __shfl_xor_sync(0xffffffffu, m, o));
    __shared__ float wmax[16];
    if ((t & 31) == 0) wmax[t >> 5] = m;
    __syncthreads();
    m = wmax[0];
    #pragma unroll
    for (int i = 1; i < 16; ++i) m = fmaxf(m, wmax[i]);

    const float scale = fmaxf(m, 1e-6f);
    const float inv_scale = __fdividef(1.0f, scale);

    // ---- scalars / per-step constants ----
    const float a  = *a_p;
    const float b  = *b_p;
    const float dt = *dt_p;
    const int   n_steps = ns_p ? *ns_p : 8;

    const float alpha = dt / FHN_TAU;
    const float denom = 1.0f + alpha * b;
    const float k1 = 1.0f / denom;
    const float k2 = alpha / denom;
    const float k3 = alpha * a / denom;
    const float c1 = 1.0f + dt;              // v_pre = v*(c1 - c3*v^2) + s
    const float c3 = dt * (1.0f / 3.0f);

    // s-recurrence: s = P - dt*w;  s' = k1*s + nck*v_pre + P2
    const float omk1 = 1.0f - k1;
    const float ndk3 = -dt * k3;
    const float nck  = -dt * k2;

    const ull C1  = pk2(c1, c1);
    const ull NC3 = pk2(-c3, -c3);
    const ull K1  = pk2(k1, k1);
    const ull NCK = pk2(nck, nck);

    // ---- stimulus conditioning ----
    const float di = dt * inv_scale;
    float xs[4] = {x.x, x.y, x.z, x.w};
    float p[4], p2[4];
    #pragma unroll
    for (int i = 0; i < 4; ++i) {
        float xv = xs[i];
        float ax = fabsf(xv);
        float e  = __expf(fmaf(-10.0f, ax, 5.0f));      // exp(-(|x|-0.5)*10)
        float g  = __fdividef(1.0f, 1.0f + e);          // sigmoid
        float P  = (di * xv) * fmaf(0.9f, g, 0.1f);
        p[i]  = P;                                      // s0 = P  (w0 = 0)
        p2[i] = fmaf(omk1, P, ndk3);
    }

    ull P2[2], V[2], S[2];
    #pragma unroll
    for (int j = 0; j < 2; ++j) {
        S[j]  = pk2(p[2 * j], p[2 * j + 1]);
        P2[j] = pk2(p2[2 * j], p2[2 * j + 1]);
        V[j]  = 0ull;
    }

    // ---- IMEX loop: 5 packed FMA-pipe ops + clip per pair per step ----
    for (int s = 0; s < n_steps; ++s) {
        #pragma unroll
        for (int j = 0; j < 2; ++j) {
            ull T  = mul2(V[j], V[j]);             // v^2
            ull R  = fma2(NC3, T, C1);             // c1 - c3*v^2
            ull Vp = fma2(R, V[j], S[j]);          // v_pre
            S[j]   = fma2(K1, S[j], fma2(NCK, Vp, P2[j]));
            V[j]   = clip2(Vp);
        }
    }

    // ---- outputs: response = v*scale at [0,N), v at [N,2N) ----
    const ull SC = pk2(scale, scale);
    UF v0, v1, r0, r1;
    v0.u = V[0]; v1.u = V[1];
    r0.u = mul2(V[0], SC); r1.u = mul2(V[1], SC);

    float4* o4 = reinterpret_cast<float4*>(out + base);
    o4[t] = make_float4(r0.f.x, r0.f.y, r1.f.x, r1.f.y);

    if (writeV) {
        float4* v4 = reinterpret_cast<float4*>(out + N + base);
        v4[t] = make_float4(v0.f.x, v0.f.y, v1.f.x, v1.f.y);
    }
}

extern "C" void kernel_launch(void* const* d_in, const int* in_sizes, int n_in,
                              void* d_out, int out_size)
{
    const float* stim = (const float*)d_in[0];
    const float* a    = (const float*)d_in[1];
    const float* b    = (const float*)d_in[2];
    const float* dt   = (const float*)d_in[3];
    const int*   ns   = (n_in > 4) ? (const int*)d_in[4] : nullptr;

    long long N = (long long)in_sizes[0];          // 33,554,432
    int rows = (int)(N / 2048);                    // 16384 CTAs
    int writeV = ((long long)out_size >= 2 * N) ? 1 : 0;

    fhn_kernel<<<rows, 512>>>(stim, a, b, dt, ns, (float*)d_out, N, writeV);
}

// round 6
// speedup vs baseline: 1.4271x; 1.4271x over previous
#include <cuda_runtime.h>
#include <cuda_bf16.h>

// FHN IMEX dynamics, (4,4096,2048) fp32, 8 steps.
// One CTA (256 threads) per 2048-element row; 8 elements/thread (two float4).
// s = P - dt*w folding: 5 packed f32x2 FMA-pipe ops + 4 FMNMX per pair/step.
// Fully-unrolled 8-step fast path (n_steps==8) for cross-step scheduling.
// Streaming loads/stores (.cs) for once-touched data.

#define FHN_TAU 12.5f

typedef unsigned long long ull;

union UF { ull u; float2 f; };

__device__ __forceinline__ ull pk2(float lo, float hi) {
    UF r; r.f.x = lo; r.f.y = hi; return r.u;
}
__device__ __forceinline__ ull fma2(ull a, ull b, ull c) {
    ull d; asm("fma.rn.f32x2 %0, %1, %2, %3;" : "=l"(d) : "l"(a), "l"(b), "l"(c)); return d;
}
__device__ __forceinline__ ull mul2(ull a, ull b) {
    ull d; asm("mul.rn.f32x2 %0, %1, %2;" : "=l"(d) : "l"(a), "l"(b)); return d;
}
__device__ __forceinline__ ull clip2(ull x) {
    UF v; v.u = x;
    v.f.x = fminf(fmaxf(v.f.x, -3.0f), 3.0f);
    v.f.y = fminf(fmaxf(v.f.y, -3.0f), 3.0f);
    return v.u;
}

__global__ __launch_bounds__(256, 5)
void fhn_kernel(const float* __restrict__ stim,
                const float* __restrict__ a_p,
                const float* __restrict__ b_p,
                const float* __restrict__ dt_p,
                const int*   __restrict__ ns_p,
                float* __restrict__ out,
                long long N, int writeV)
{
    const int  C    = 2048;
    const int  t    = threadIdx.x;
    const long long base = (long long)blockIdx.x * C;

    // ---- load 8 elements as two coalesced float4 (streaming) ----
    const float4* s4 = reinterpret_cast<const float4*>(stim + base);
    float4 x0 = __ldcs(s4 + t);
    float4 x1 = __ldcs(s4 + t + 256);

    // ---- row max(|x|) reduction ----
    float m = fmaxf(fmaxf(fmaxf(fabsf(x0.x), fabsf(x0.y)), fmaxf(fabsf(x0.z), fabsf(x0.w))),
                    fmaxf(fmaxf(fabsf(x1.x), fabsf(x1.y)), fmaxf(fabsf(x1.z), fabsf(x1.w))));
    #pragma unroll
    for (int o = 16; o > 0; o >>= 1)
        m = fmaxf(m, __shfl_xor_sync(0xffffffffu, m, o));
    __shared__ float wmax[8];
    if ((t & 31) == 0) wmax[t >> 5] = m;
    __syncthreads();
    m = wmax[0];
    #pragma unroll
    for (int i = 1; i < 8; ++i) m = fmaxf(m, wmax[i]);

    const float scale = fmaxf(m, 1e-6f);
    const float inv_scale = __fdividef(1.0f, scale);

    // ---- scalars / per-step constants ----
    const float a  = *a_p;
    const float b  = *b_p;
    const float dt = *dt_p;
    const int   n_steps = ns_p ? *ns_p : 8;

    const float alpha = dt / FHN_TAU;
    const float denom = 1.0f + alpha * b;
    const float k1 = 1.0f / denom;
    const float k2 = alpha / denom;
    const float k3 = alpha * a / denom;
    const float c1 = 1.0f + dt;              // v_pre = v*(c1 - c3*v^2) + s
    const float c3 = dt * (1.0f / 3.0f);

    // s-recurrence: s = P - dt*w;  s' = k1*s + nck*v_pre + P2
    const float omk1 = 1.0f - k1;
    const float ndk3 = -dt * k3;
    const float nck  = -dt * k2;

    const ull C1  = pk2(c1, c1);
    const ull NC3 = pk2(-c3, -c3);
    const ull K1  = pk2(k1, k1);
    const ull NCK = pk2(nck, nck);

    // ---- stimulus conditioning:
    //   I = (x/scale)*(0.1 + 0.9*sigmoid((|x|-0.5)*10));  P = dt*I; s0 = P
    //   P2 = (1-k1)*P - dt*k3
    const float di = dt * inv_scale;
    float xs[8] = {x0.x, x0.y, x0.z, x0.w, x1.x, x1.y, x1.z, x1.w};
    float p[8], p2[8];
    #pragma unroll
    for (int i = 0; i < 8; ++i) {
        float xv = xs[i];
        float ax = fabsf(xv);
        float e  = __expf(fmaf(-10.0f, ax, 5.0f));      // exp(-(|x|-0.5)*10)
        float g  = __fdividef(1.0f, 1.0f + e);          // sigmoid
        float P  = (di * xv) * fmaf(0.9f, g, 0.1f);
        p[i]  = P;
        p2[i] = fmaf(omk1, P, ndk3);
    }

    ull P2[4], V[4], S[4];
    #pragma unroll
    for (int j = 0; j < 4; ++j) {
        S[j]  = pk2(p[2 * j], p[2 * j + 1]);
        P2[j] = pk2(p2[2 * j], p2[2 * j + 1]);
        V[j]  = 0ull;
    }

#define FHN_STEP(j)                                             \
    do {                                                        \
        ull T  = mul2(V[j], V[j]);                              \
        ull R  = fma2(NC3, T, C1);                              \
        ull Vp = fma2(R, V[j], S[j]);                           \
        S[j]   = fma2(K1, S[j], fma2(NCK, Vp, P2[j]));          \
        V[j]   = clip2(Vp);                                     \
    } while (0)

    if (n_steps == 8) {
        // fully-unrolled straight-line body: 8 steps x 4 independent pairs
        #pragma unroll
        for (int s = 0; s < 8; ++s) {
            FHN_STEP(0); FHN_STEP(1); FHN_STEP(2); FHN_STEP(3);
        }
    } else {
        for (int s = 0; s < n_steps; ++s) {
            FHN_STEP(0); FHN_STEP(1); FHN_STEP(2); FHN_STEP(3);
        }
    }
#undef FHN_STEP

    // ---- outputs: response = v*scale at [0,N), v at [N,2N) (streaming) ----
    const ull SC = pk2(scale, scale);
    UF v0, v1, v2, v3, r0, r1, r2, r3;
    v0.u = V[0]; v1.u = V[1]; v2.u = V[2]; v3.u = V[3];
    r0.u = mul2(V[0], SC); r1.u = mul2(V[1], SC);
    r2.u = mul2(V[2], SC); r3.u = mul2(V[3], SC);

    float4* o4 = reinterpret_cast<float4*>(out + base);
    __stcs(o4 + t,       make_float4(r0.f.x, r0.f.y, r1.f.x, r1.f.y));
    __stcs(o4 + t + 256, make_float4(r2.f.x, r2.f.y, r3.f.x, r3.f.y));

    if (writeV) {
        float4* v4 = reinterpret_cast<float4*>(out + N + base);
        __stcs(v4 + t,       make_float4(v0.f.x, v0.f.y, v1.f.x, v1.f.y));
        __stcs(v4 + t + 256, make_float4(v2.f.x, v2.f.y, v3.f.x, v3.f.y));
    }
}

extern "C" void kernel_launch(void* const* d_in, const int* in_sizes, int n_in,
                              void* d_out, int out_size)
{
    const float* stim = (const float*)d_in[0];
    const float* a    = (const float*)d_in[1];
    const float* b    = (const float*)d_in[2];
    const float* dt   = (const float*)d_in[3];
    const int*   ns   = (n_in > 4) ? (const int*)d_in[4] : nullptr;

    long long N = (long long)in_sizes[0];          // 33,554,432
    int rows = (int)(N / 2048);                    // 16384 CTAs
    int writeV = ((long long)out_size >= 2 * N) ? 1 : 0;

    fhn_kernel<<<rows, 256>>>(stim, a, b, dt, ns, (float*)d_out, N, writeV);
}